// round 12
// baseline (speedup 1.0000x reference)
#include <cuda_runtime.h>
#include <cstdint>

#define B 32
#define T_IN 512
#define T_OUT 2048
#define ADIM 384
#define PDIM 4
#define NV (ADIM / 4)          // 96 float4 per row
#define QB 224                 // worker-quads per batch: 896 workers (512 scatter + 384 embed-only)
#define NTHR 384

// Scratch: per-batch inclusive cumsum of masked durations.
__device__ int g_cum[B * T_IN];

// -------- Kernel 1: durations -> masked inclusive cumsum --------
// Integer inputs may be int32 or int64 (jax default config downcasts int64 ->
// int32). Durations are in [1,4]; for little-endian int64 odd words are 0.
__global__ void prep_kernel(const int* __restrict__ dur32,
                            const int* __restrict__ ilen32) {
    const int b = blockIdx.x;
    const int t = threadIdx.x;                 // 512 threads == T_IN

    __shared__ int cum[T_IN];

    const bool is64 = (dur32[1] == 0);
    const int L = is64 ? ilen32[2 * b] : ilen32[b];

    int d = 0;
    if (t < L) {
        const int k = b * T_IN + t;
        d = is64 ? dur32[2 * k] : dur32[k];
    }

    cum[t] = d;
    __syncthreads();
    #pragma unroll
    for (int off = 1; off < T_IN; off <<= 1) {
        int v = (t >= off) ? cum[t - off] : 0;
        __syncthreads();
        cum[t] += v;
        __syncthreads();
    }

    // torch semantics: if total == 0, valid positions get duration 1.
    int c = cum[t];
    if (cum[T_IN - 1] == 0) c = min(t + 1, L);

    g_cum[b * T_IN + t] = c;
}

// -------- Kernel 2: scatter (phone -> 1..4 output rows) + embed-only tail ----
__device__ __forceinline__ float4 row_embed(const float4 pt, const float et,
                                            const float4 w0, const float4 w1,
                                            const float4 w2, const float4 w3,
                                            const float4 ewv, const float4 bias) {
    float4 r;
    r.x = fmaf(et, ewv.x, bias.x);
    r.y = fmaf(et, ewv.y, bias.y);
    r.z = fmaf(et, ewv.z, bias.z);
    r.w = fmaf(et, ewv.w, bias.w);
    r.x = fmaf(pt.x, w0.x, fmaf(pt.y, w0.y, fmaf(pt.z, w0.z, fmaf(pt.w, w0.w, r.x))));
    r.y = fmaf(pt.x, w1.x, fmaf(pt.y, w1.y, fmaf(pt.z, w1.z, fmaf(pt.w, w1.w, r.y))));
    r.z = fmaf(pt.x, w2.x, fmaf(pt.y, w2.y, fmaf(pt.z, w2.z, fmaf(pt.w, w2.w, r.z))));
    r.w = fmaf(pt.x, w3.x, fmaf(pt.y, w3.y, fmaf(pt.z, w3.z, fmaf(pt.w, w3.w, r.w))));
    return r;
}

__global__ void __launch_bounds__(NTHR)
main_kernel(const float* __restrict__ hs,
            const float* __restrict__ pitch_target,
            const float* __restrict__ energy_target,
            const float* __restrict__ pitch_w,   // [ADIM, 4]
            const float* __restrict__ pitch_b,   // [ADIM]
            const float* __restrict__ energy_w,  // [ADIM]
            const float* __restrict__ energy_b,  // [ADIM]
            float* __restrict__ out) {
    const int tx = threadIdx.x;                 // 0..95 (channel group)
    const int ty = threadIdx.y;                 // 0..3  (worker within block)
    const int bb = blockIdx.x / QB;             // batch
    const int q  = blockIdx.x % QB;
    const int w  = q * 4 + ty;                  // worker id 0..895 (warp-uniform)
    const int a  = tx * 4;

    // Weights/biases into registers.
    const float4 w0 = *reinterpret_cast<const float4*>(pitch_w + (a + 0) * 4);
    const float4 w1 = *reinterpret_cast<const float4*>(pitch_w + (a + 1) * 4);
    const float4 w2 = *reinterpret_cast<const float4*>(pitch_w + (a + 2) * 4);
    const float4 w3 = *reinterpret_cast<const float4*>(pitch_w + (a + 3) * 4);
    const float4 pbv = *reinterpret_cast<const float4*>(pitch_b + a);
    const float4 ewv = *reinterpret_cast<const float4*>(energy_w + a);
    const float4 ebv = *reinterpret_cast<const float4*>(energy_b + a);
    float4 bias;
    bias.x = pbv.x + ebv.x; bias.y = pbv.y + ebv.y;
    bias.z = pbv.z + ebv.z; bias.w = pbv.w + ebv.w;

    const int* __restrict__ cumb = g_cum + bb * T_IN;
    const float* __restrict__ ptb = pitch_target + (size_t)bb * T_OUT * PDIM;
    const float* __restrict__ etb = energy_target + (size_t)bb * T_OUT;
    float4* __restrict__ outb = reinterpret_cast<float4*>(out)
                                + (size_t)bb * T_OUT * NV + tx;

    const int total = __ldg(cumb + T_IN - 1);

    if (w < T_IN) {
        // ---- Scatter worker: phone w -> output rows [lo, hi) (0..4 rows) ----
        const int lo = (w > 0) ? __ldg(cumb + w - 1) : 0;
        const int hi = __ldg(cumb + w);
        if (lo < hi) {
            const float4 h = __ldg(reinterpret_cast<const float4*>(hs)
                                   + ((size_t)bb * T_IN + w) * NV + tx);
            #pragma unroll
            for (int k = 0; k < 4; k++) {
                const int r = lo + k;
                if (r < hi) {
                    const float4 pt = __ldg(reinterpret_cast<const float4*>(
                        ptb + (size_t)r * PDIM));
                    const float et = __ldg(etb + r);
                    float4 v = row_embed(pt, et, w0, w1, w2, w3, ewv, bias);
                    v.x += h.x; v.y += h.y; v.z += h.z; v.w += h.w;
                    __stcs(outb + (size_t)r * NV, v);
                }
            }
        }
    } else {
        // ---- Embed-only worker: 4 frame-masked rows starting at total ----
        const int base = total + (w - T_IN) * 4;
        #pragma unroll
        for (int k = 0; k < 4; k++) {
            const int r = base + k;
            if (r < T_OUT) {
                const float4 pt = __ldg(reinterpret_cast<const float4*>(
                    ptb + (size_t)r * PDIM));
                const float et = __ldg(etb + r);
                float4 v = row_embed(pt, et, w0, w1, w2, w3, ewv, bias);
                __stcs(outb + (size_t)r * NV, v);
            }
        }
    }
}

extern "C" void kernel_launch(void* const* d_in, const int* in_sizes, int n_in,
                              void* d_out, int out_size) {
    const float* hs   = (const float*)d_in[0];
    const int*   dur  = (const int*)d_in[1];   // int32 or int64 (probed in-kernel)
    const int*   ilen = (const int*)d_in[2];
    const float* pt   = (const float*)d_in[3];
    const float* et   = (const float*)d_in[4];
    // d_in[5], d_in[6]: duration_mask / variance_mask (unused, all false)
    const float* pw   = (const float*)d_in[7];
    const float* pb   = (const float*)d_in[8];
    const float* ew   = (const float*)d_in[9];
    const float* eb   = (const float*)d_in[10];
    float*       out  = (float*)d_out;

    prep_kernel<<<B, T_IN>>>(dur, ilen);

    dim3 blk(NV, 4);                            // 96 x 4 = 384 threads
    main_kernel<<<B * QB, blk>>>(hs, pt, et, pw, pb, ew, eb, out);
}

// round 13
// speedup vs baseline: 1.7436x; 1.7436x over previous
#include <cuda_runtime.h>
#include <cstdint>

#define B 32
#define T_IN 512
#define T_OUT 2048
#define ADIM 384
#define PDIM 4
#define NROWS (B * T_OUT)
#define NV (ADIM / 4)          // 96 float4 per row
#define CHUNK 64               // contiguous rows per block (divides T_OUT)
#define GRID_MAIN (NROWS / CHUNK)   // 1024 blocks

// Scratch: source index per output frame, -1 = padded (zero) frame.
__device__ int g_idx[NROWS];

// -------- Kernel 1: durations -> cumsum -> searchsorted indices --------
// Integer inputs may be int32 or int64 (jax default config downcasts int64 ->
// int32). Durations are in [1,4]; for little-endian int64 odd words are 0.
__global__ void prep_kernel(const int* __restrict__ dur32,
                            const int* __restrict__ ilen32) {
    // Let the dependent (main) kernel launch immediately; it synchronizes
    // before consuming g_idx.
    cudaTriggerProgrammaticLaunchCompletion();

    const int b = blockIdx.x;
    const int t = threadIdx.x;                 // 512 threads == T_IN

    __shared__ int cum[T_IN];

    const bool is64 = (dur32[1] == 0);
    const int L = is64 ? ilen32[2 * b] : ilen32[b];

    int d = 0;
    if (t < L) {
        const int k = b * T_IN + t;
        d = is64 ? dur32[2 * k] : dur32[k];
    }

    cum[t] = d;
    __syncthreads();
    #pragma unroll
    for (int off = 1; off < T_IN; off <<= 1) {
        int v = (t >= off) ? cum[t - off] : 0;
        __syncthreads();
        cum[t] += v;
        __syncthreads();
    }

    // torch semantics: if total == 0, valid positions get duration 1.
    if (cum[T_IN - 1] == 0) {
        cum[t] = min(t + 1, L);
        __syncthreads();
    }

    const int total = cum[T_IN - 1];

    for (int to = t; to < T_OUT; to += T_IN) {
        int lo = 0, hi = T_IN;
        while (lo < hi) {
            int mid = (lo + hi) >> 1;
            if (cum[mid] <= to) lo = mid + 1; else hi = mid;
        }
        int idx = min(lo, T_IN - 1);
        g_idx[b * T_OUT + to] = (to < total) ? idx : -1;
    }
}

// -------- Kernel 2 (PDL dependent): smem-staged metadata + MLP2 gathers -----
__device__ __forceinline__ float4 row_embed(const float4 pt, const float et,
                                            const float4 w0, const float4 w1,
                                            const float4 w2, const float4 w3,
                                            const float4 ewv, const float4 bias) {
    float4 r;
    r.x = fmaf(et, ewv.x, bias.x);
    r.y = fmaf(et, ewv.y, bias.y);
    r.z = fmaf(et, ewv.z, bias.z);
    r.w = fmaf(et, ewv.w, bias.w);
    r.x = fmaf(pt.x, w0.x, fmaf(pt.y, w0.y, fmaf(pt.z, w0.z, fmaf(pt.w, w0.w, r.x))));
    r.y = fmaf(pt.x, w1.x, fmaf(pt.y, w1.y, fmaf(pt.z, w1.z, fmaf(pt.w, w1.w, r.y))));
    r.z = fmaf(pt.x, w2.x, fmaf(pt.y, w2.y, fmaf(pt.z, w2.z, fmaf(pt.w, w2.w, r.z))));
    r.w = fmaf(pt.x, w3.x, fmaf(pt.y, w3.y, fmaf(pt.z, w3.z, fmaf(pt.w, w3.w, r.w))));
    return r;
}

__global__ void __launch_bounds__(NV * 4)
main_kernel(const float* __restrict__ hs,
            const float* __restrict__ pitch_target,
            const float* __restrict__ energy_target,
            const float* __restrict__ pitch_w,   // [ADIM, 4]
            const float* __restrict__ pitch_b,   // [ADIM]
            const float* __restrict__ energy_w,  // [ADIM]
            const float* __restrict__ energy_b,  // [ADIM]
            float* __restrict__ out) {
    __shared__ int    s_idx[CHUNK];
    __shared__ float4 s_pt[CHUNK];
    __shared__ float  s_et[CHUNK];

    const int tx = threadIdx.x;                 // 0..95 (channel group)
    const int ty = threadIdx.y;                 // 0..3
    const int tid = ty * NV + tx;               // 0..383
    const int row0 = blockIdx.x * CHUNK;
    const int a = tx * 4;

    // ---- Prep-independent prologue (overlaps with prep_kernel via PDL) ----
    if (tid < CHUNK) {
        s_et[tid] = energy_target[row0 + tid];
    } else if (tid < CHUNK + 4 * CHUNK) {       // 64..319 -> 256 pt words
        const int j = tid - CHUNK;
        reinterpret_cast<float*>(s_pt)[j] = pitch_target[row0 * PDIM + j];
    }

    const float4 w0 = *reinterpret_cast<const float4*>(pitch_w + (a + 0) * 4);
    const float4 w1 = *reinterpret_cast<const float4*>(pitch_w + (a + 1) * 4);
    const float4 w2 = *reinterpret_cast<const float4*>(pitch_w + (a + 2) * 4);
    const float4 w3 = *reinterpret_cast<const float4*>(pitch_w + (a + 3) * 4);
    const float4 pbv = *reinterpret_cast<const float4*>(pitch_b + a);
    const float4 ewv = *reinterpret_cast<const float4*>(energy_w + a);
    const float4 ebv = *reinterpret_cast<const float4*>(energy_b + a);
    float4 bias;
    bias.x = pbv.x + ebv.x; bias.y = pbv.y + ebv.y;
    bias.z = pbv.z + ebv.z; bias.w = pbv.w + ebv.w;

    // ---- Wait for prep_kernel's g_idx to be globally visible ----
    cudaGridDependencySynchronize();

    if (tid < CHUNK) {
        s_idx[tid] = g_idx[row0 + tid];
    }
    __syncthreads();

    // All rows of this block share one batch (CHUNK divides T_OUT).
    const float* __restrict__ hsb = hs + (size_t)(row0 / T_OUT) * T_IN * ADIM + a;
    float* __restrict__ outb = out + (size_t)row0 * ADIM + a;

    // 16 rows per thread, processed in batches of 2 (both gathers in flight).
    #pragma unroll
    for (int ii = 0; ii < CHUNK / 4; ii += 2) {
        const int lr0 = ii * 4 + ty;
        const int lr1 = lr0 + 4;
        const int i0 = s_idx[lr0];
        const int i1 = s_idx[lr1];

        float4 h0 = make_float4(0.f, 0.f, 0.f, 0.f);
        float4 h1 = make_float4(0.f, 0.f, 0.f, 0.f);
        if (i0 >= 0) h0 = __ldg(reinterpret_cast<const float4*>(hsb + (size_t)i0 * ADIM));
        if (i1 >= 0) h1 = __ldg(reinterpret_cast<const float4*>(hsb + (size_t)i1 * ADIM));

        float4 r0 = row_embed(s_pt[lr0], s_et[lr0], w0, w1, w2, w3, ewv, bias);
        float4 r1 = row_embed(s_pt[lr1], s_et[lr1], w0, w1, w2, w3, ewv, bias);
        r0.x += h0.x; r0.y += h0.y; r0.z += h0.z; r0.w += h0.w;
        r1.x += h1.x; r1.y += h1.y; r1.z += h1.z; r1.w += h1.w;

        __stcs(reinterpret_cast<float4*>(outb + (size_t)lr0 * ADIM), r0);
        __stcs(reinterpret_cast<float4*>(outb + (size_t)lr1 * ADIM), r1);
    }
}

extern "C" void kernel_launch(void* const* d_in, const int* in_sizes, int n_in,
                              void* d_out, int out_size) {
    const float* hs   = (const float*)d_in[0];
    const int*   dur  = (const int*)d_in[1];   // int32 or int64 (probed in-kernel)
    const int*   ilen = (const int*)d_in[2];
    const float* pt   = (const float*)d_in[3];
    const float* et   = (const float*)d_in[4];
    // d_in[5], d_in[6]: duration_mask / variance_mask (unused, all false)
    const float* pw   = (const float*)d_in[7];
    const float* pb   = (const float*)d_in[8];
    const float* ew   = (const float*)d_in[9];
    const float* eb   = (const float*)d_in[10];
    float*       out  = (float*)d_out;

    prep_kernel<<<B, T_IN>>>(dur, ilen);

    // Launch main with Programmatic Dependent Launch: it starts while prep is
    // still running and synchronizes in-kernel before reading g_idx.
    cudaLaunchConfig_t cfg = {};
    cfg.gridDim  = dim3(GRID_MAIN, 1, 1);
    cfg.blockDim = dim3(NV, 4, 1);              // 96 x 4 = 384 threads
    cfg.dynamicSmemBytes = 0;
    cfg.stream = 0;                              // legacy default stream (captured)
    cudaLaunchAttribute attrs[1];
    attrs[0].id = cudaLaunchAttributeProgrammaticStreamSerialization;
    attrs[0].val.programmaticStreamSerializationAllowed = 1;
    cfg.attrs = attrs;
    cfg.numAttrs = 1;

    cudaLaunchKernelEx(&cfg, main_kernel, hs, pt, et, pw, pb, ew, eb, out);
}